// round 14
// baseline (speedup 1.0000x reference)
#include <cuda_runtime.h>
#include <math.h>

#define T_DATA 40000
#define SUB    32
#define E_E    2000
#define E_I    400
#define TNO    200
#define NCOS   17
#define FILT_OFF (2*T_DATA)

#define PI_F   3.14159274f      // float32(pi), matches jnp
#define HPI_F  1.5707964f       // float32(pi/2)

// ---------------- scratch (no allocation allowed) ----------------
__device__ float g_syn_e[(size_t)T_DATA*SUB];
__device__ float g_syn_i[(size_t)T_DATA*SUB];
__device__ float g_syn  [(size_t)T_DATA*SUB];
__device__ float g_ke[TNO*SUB];   // transposed [tau][s]
__device__ float g_ki[TNO*SUB];
__device__ float g_hk[TNO];
__device__ float g_ok[TNO];
// one-hot fast tables: {byte_offset = s*4, float_bits(w)} per column (16B-aligned for LDG.128)
__device__ __align__(16) int2  g_etab[E_E];
__device__ __align__(16) int2  g_itab[E_I];
__device__ int   g_multi = 0;     // sticky
// generic fallback CSR (row-major, cold)
__device__ int   g_ecnt[E_E];
__device__ int   g_esub[E_E*SUB];
__device__ float g_ew  [E_E*SUB];
__device__ int   g_icnt[E_I];
__device__ int   g_isub[E_I*SUB];
__device__ float g_iw  [E_I*SUB];
__device__ int   g_ch_cnt[SUB];
__device__ int   g_ch_idx[SUB*SUB];
__device__ float g_ch_w[SUB*SUB];
// binary-heap specialization
__device__ float g_hw0[SUB];
__device__ float g_hw1[SUB];
__device__ int   g_treebad = 0;   // sticky
// effective synaptic-kernel support (multiple of 8); sticky-max, deterministic per input
__device__ int   g_L3 = 8;

// ---------------- kSetup ----------------
__global__ void kSetup(const float* __restrict__ Ce, const float* __restrict__ Ci,
                       const float* __restrict__ C_den, const float* __restrict__ W_sub,
                       const float* __restrict__ Tau_syn, const float* __restrict__ Delta_syn,
                       const float* __restrict__ W_syn,   const float* __restrict__ W_hist,
                       const float* __restrict__ Tau_out, const float* __restrict__ W_out,
                       float* __restrict__ dout) {
    int gid = blockIdx.x * blockDim.x + threadIdx.x;
    int nth = gridDim.x * blockDim.x;

    // ---- zero atomic accumulators (every replay) ----
    float4 z4 = make_float4(0.f, 0.f, 0.f, 0.f);
    float4* ze = (float4*)g_syn_e;
    float4* zi = (float4*)g_syn_i;
    for (int i = gid; i < T_DATA*SUB/4; i += nth) { ze[i] = z4; zi[i] = z4; }

    // ---- CSR + one-hot tables ----
    if (gid < E_E) {
        int e = gid;
        int c = 0; int s0 = 0; float w0 = 0.f;
        for (int s = 0; s < SUB; s++) {
            float w = Ce[(size_t)s * E_E + e];
            if (w != 0.f) {
                if (c == 0) { s0 = s; w0 = w; }
                g_esub[e*SUB + c] = s; g_ew[e*SUB + c] = w; c++;
            }
        }
        g_ecnt[e] = c;
        g_etab[e] = make_int2(s0 * 4, __float_as_int(w0));
        if (c > 1) atomicOr(&g_multi, 1);
    }
    if (gid < E_I) {
        int e = gid;
        int c = 0; int s0 = 0; float w0 = 0.f;
        for (int s = 0; s < SUB; s++) {
            float w = Ci[(size_t)s * E_I + e];
            if (w != 0.f) {
                if (c == 0) { s0 = s; w0 = w; }
                g_isub[e*SUB + c] = s; g_iw[e*SUB + c] = w; c++;
            }
        }
        g_icnt[e] = c;
        g_itab[e] = make_int2(s0 * 4, __float_as_int(w0));
        if (c > 1) atomicOr(&g_multi, 1);
    }
    if (gid < SUB) {   // children lists + heap specialization + kernel support
        int idx = gid;
        int c = 0;
        float hw0 = 0.f, hw1 = 0.f;
        bool bad = false;
        for (int j = 0; j < SUB; j++) {
            float w = C_den[idx*SUB + j];
            if (w != 0.f) {
                float ww = w * expf(W_sub[j]);
                g_ch_idx[idx*SUB + c] = j;
                g_ch_w[idx*SUB + c]   = ww;
                c++;
                if      (j == 2*idx + 1) hw0 = ww;
                else if (j == 2*idx + 2) hw1 = ww;
                else bad = true;
            }
        }
        g_ch_cnt[idx] = c;
        g_hw0[idx] = hw0;
        g_hw1[idx] = hw1;
        if (bad) atomicOr(&g_treebad, 1);

        // effective support of this subunit's alpha kernels (suffix-sum criterion)
        {
            int s = idx;
            float de  = expf(Delta_syn[s*2 + 0]);
            float ite = 1.f / expf(Tau_syn[s*2 + 0]);
            float we  = expf(W_syn[s*2 + 0]);
            float di  = expf(Delta_syn[s*2 + 1]);
            float iti = 1.f / expf(Tau_syn[s*2 + 1]);
            float wi  = expf(W_syn[s*2 + 1]);
            float tail = 0.f;
            int L = 8;
            for (int tau = TNO - 1; tau >= 0; tau--) {
                float t = (float)tau;
                float tte = fmaxf(t - de, 0.f) * ite;
                float tti = fmaxf(t - di, 0.f) * iti;
                float ek  = tte * expf(-tte) * we;
                float ik  = tti * expf(-tti) * wi;
                tail += fabsf(ek) + fabsf(ik);
                if (tail > 1e-10f) { L = tau + 2; break; }
            }
            L = min(TNO, ((L + 7) / 8) * 8);
            atomicMax(&g_L3, L);
        }
    }

    // ---- alpha kernels + out_filters ----
    for (int i = gid; i < SUB * TNO; i += nth) {
        int s = i / TNO, tau = i % TNO;
        float t = (float)tau;
        float te  = fmaxf(t - expf(Delta_syn[s*2 + 0]), 0.f);
        float tte = te / expf(Tau_syn[s*2 + 0]);
        float ek  = tte * expf(-tte) * expf(W_syn[s*2 + 0]);
        float ti  = fmaxf(t - expf(Delta_syn[s*2 + 1]), 0.f);
        float tti = ti / expf(Tau_syn[s*2 + 1]);
        float ik  = -tti * expf(-tti) * expf(W_syn[s*2 + 1]);
        g_ke[tau*SUB + s] = ek;
        g_ki[tau*SUB + s] = ik;
        dout[FILT_OFF + s*TNO + tau]           = ek;
        dout[FILT_OFF + SUB*TNO + s*TNO + tau] = ik;
    }
    for (int tau = gid; tau < TNO; tau += nth) {
        float raw = 4.f * logf((float)tau + 1.f);
        float hk = 0.f;
        #pragma unroll
        for (int n = 0; n < NCOS; n++) {
            float phi = HPI_F * (float)n;
            if (raw >= phi - PI_F && raw <= phi + PI_F)
                hk -= expf(W_hist[n]) * (0.5f * cosf(raw - phi) + 0.5f);
        }
        g_hk[tau] = hk;
        dout[FILT_OFF + 2*SUB*TNO + tau] = hk;

        float tto = (float)tau / expf(Tau_out[0]);
        g_ok[tau] = tto * expf(-tto) * expf(W_out[0]);
    }
}

// ---------------- K1: lean predicated spike scatter, tables loaded only on hit ----------------
__device__ __forceinline__ void spk(float v, int off, float w, float* dst) {
    asm volatile(
        "{\n\t"
        ".reg .pred p;\n\t"
        ".reg .b64 ra;\n\t"
        ".reg .f32 fv;\n\t"
        "setp.ne.f32 p, %0, 0f00000000;\n\t"
        "@p mad.wide.u32 ra, %1, 1, %3;\n\t"
        "@p mul.f32 fv, %0, %2;\n\t"
        "@p red.global.add.f32 [ra], fv;\n\t"
        "}" :: "f"(v), "r"((unsigned)off), "f"(w), "l"(dst));
}

// predicated pair of LDG.128: no LSU wavefronts when the quad is all-zero (~92%)
__device__ __forceinline__ void ldtab(unsigned m, const int4* tb, int4& p0, int4& p1) {
    asm volatile(
        "{\n\t"
        ".reg .pred p;\n\t"
        "setp.ne.u32 p, %8, 0;\n\t"
        "@p ld.global.nc.v4.b32 {%0,%1,%2,%3}, [%9];\n\t"
        "@p ld.global.nc.v4.b32 {%4,%5,%6,%7}, [%9+16];\n\t"
        "}"
        : "=r"(p0.x), "=r"(p0.y), "=r"(p0.z), "=r"(p0.w),
          "=r"(p1.x), "=r"(p1.y), "=r"(p1.z), "=r"(p1.w)
        : "r"(m), "l"(tb));
}

__device__ __forceinline__ void proc_e(float4 v, int q) {
    unsigned m = __float_as_uint(v.x) | __float_as_uint(v.y)
               | __float_as_uint(v.z) | __float_as_uint(v.w);
    unsigned t = (unsigned)q / 500u;
    int e0 = (q - (int)t * 500) * 4;
    float* dst = g_syn_e + (size_t)t * SUB;
    int4 p0, p1;
    ldtab(m, (const int4*)(g_etab + e0), p0, p1);
    spk(v.x, p0.x, __int_as_float(p0.y), dst);
    spk(v.y, p0.z, __int_as_float(p0.w), dst);
    spk(v.z, p1.x, __int_as_float(p1.y), dst);
    spk(v.w, p1.z, __int_as_float(p1.w), dst);
}
__device__ __forceinline__ void proc_i(float4 v, int q) {
    unsigned m = __float_as_uint(v.x) | __float_as_uint(v.y)
               | __float_as_uint(v.z) | __float_as_uint(v.w);
    unsigned t = (unsigned)q / 100u;
    int e0 = (q - (int)t * 100) * 4;
    float* dst = g_syn_i + (size_t)t * SUB;
    int4 p0, p1;
    ldtab(m, (const int4*)(g_itab + e0), p0, p1);
    spk(v.x, p0.x, __int_as_float(p0.y), dst);
    spk(v.y, p0.z, __int_as_float(p0.w), dst);
    spk(v.z, p1.x, __int_as_float(p1.y), dst);
    spk(v.w, p1.z, __int_as_float(p1.w), dst);
}

__global__ void __launch_bounds__(256, 3) k1_proj(const float* __restrict__ Se,
                                                  const float* __restrict__ Si) {
    int gt  = blockIdx.x * blockDim.x + threadIdx.x;
    int nth = gridDim.x * blockDim.x;

    {
        const float4* p = (const float4*)Se;
        const int H = T_DATA * (E_E/4) / 2;     // 10,000,000
        int q = gt;
        if (q < H) {
            float4 a0 = __ldcs(p + q);
            float4 b0 = __ldcs(p + q + H);
            for (;;) {
                int q2 = q + nth;
                bool have = q2 < H;
                float4 a1, b1;
                if (have) { a1 = __ldcs(p + q2); b1 = __ldcs(p + q2 + H); }
                proc_e(a0, q);
                proc_e(b0, q + H);
                if (!have) break;
                a0 = a1; b0 = b1; q = q2;
            }
        }
    }
    {
        const float4* p = (const float4*)Si;
        const int H = T_DATA * (E_I/4) / 2;     // 2,000,000
        int q = gt;
        if (q < H) {
            float4 a0 = __ldcs(p + q);
            float4 b0 = __ldcs(p + q + H);
            for (;;) {
                int q2 = q + nth;
                bool have = q2 < H;
                float4 a1, b1;
                if (have) { a1 = __ldcs(p + q2); b1 = __ldcs(p + q2 + H); }
                proc_i(a0, q);
                proc_i(b0, q + H);
                if (!have) break;
                a0 = a1; b0 = b1; q = q2;
            }
        }
    }

    // ---- generic fallback for non-one-hot columns (never taken for this data) ----
    if (__ldg(&g_multi) != 0) {
        for (int e = gt; e < E_E; e += nth) {
            int c = g_ecnt[e];
            if (c > 1) {
                for (int t = 0; t < T_DATA; t++) {
                    float v = Se[(size_t)t * E_E + e];
                    if (v != 0.f)
                        for (int k = 1; k < c; k++)
                            atomicAdd(g_syn_e + (size_t)t*SUB + g_esub[e*SUB+k], v * g_ew[e*SUB+k]);
                }
            }
        }
        for (int e = gt; e < E_I; e += nth) {
            int c = g_icnt[e];
            if (c > 1) {
                for (int t = 0; t < T_DATA; t++) {
                    float v = Si[(size_t)t * E_I + e];
                    if (v != 0.f)
                        for (int k = 1; k < c; k++)
                            atomicAdd(g_syn_i + (size_t)t*SUB + g_isub[e*SUB+k], v * g_iw[e*SUB+k]);
                }
            }
        }
    }
}

// ---------------- K3: depthwise causal conv, truncated to effective support ----------------
__device__ __forceinline__ void ffma2(unsigned long long& d,
                                      unsigned long long a, unsigned long long b) {
    asm("fma.rn.f32x2 %0, %1, %2, %0;" : "+l"(d) : "l"(a), "l"(b));
}

#define TB3   272
#define NT3   544
#define ROWS3 (TB3 + TNO)                      // 472
#define SMEM3 (ROWS3 * SUB * 2 * (int)sizeof(float))  // 120832 B

__global__ void __launch_bounds__(NT3) k3_conv() {
    extern __shared__ float sh[];
    float* se_sh = sh;                   // [ROWS3][32] absolute layout
    float* si_sh = sh + ROWS3 * SUB;

    int t0 = blockIdx.x * TB3;
    int L  = g_L3;
    if (L > TNO) L = TNO;
    int row0 = TNO - L;

    {
        const float4* ge = (const float4*)g_syn_e;
        const float4* gi = (const float4*)g_syn_i;
        float4* de = (float4*)se_sh;
        float4* di = (float4*)si_sh;
        float4 z = make_float4(0.f, 0.f, 0.f, 0.f);
        for (int l = threadIdx.x + row0 * 8; l < ROWS3 * 8; l += NT3) {
            int row = l >> 3, c = l & 7;
            int g = t0 - TNO + row;
            if (g >= 0 && g < T_DATA) { de[l] = ge[g*8 + c]; di[l] = gi[g*8 + c]; }
            else                      { de[l] = z;           di[l] = z;           }
        }
    }
    __syncthreads();

    int lane  = threadIdx.x & 31, wid = threadIdx.x >> 5;
    int p     = lane & 15;
    int tslot = lane >> 4;
    int ob    = wid * 16 + tslot * 8;

    const unsigned long long* se2 = (const unsigned long long*)se_sh;
    const unsigned long long* si2 = (const unsigned long long*)si_sh;
    const unsigned long long* ke2 = (const unsigned long long*)g_ke;
    const unsigned long long* ki2 = (const unsigned long long*)g_ki;

    unsigned long long acc[8];
    #pragma unroll
    for (int i = 0; i < 8; i++) acc[i] = 0ull;

    for (int tb = 0; tb < L; tb += 8) {
        int rbase = ob + 192 - tb;
        unsigned long long kk[8], ss[15];

        #pragma unroll
        for (int j = 0; j < 8; j++) kk[j] = __ldg(&ke2[(tb + j)*16 + p]);
        #pragma unroll
        for (int m = 0; m < 15; m++) ss[m] = se2[(rbase + m)*16 + p];
        #pragma unroll
        for (int i = 0; i < 8; i++)
            #pragma unroll
            for (int j = 0; j < 8; j++)
                ffma2(acc[i], kk[j], ss[7 + i - j]);

        #pragma unroll
        for (int j = 0; j < 8; j++) kk[j] = __ldg(&ki2[(tb + j)*16 + p]);
        #pragma unroll
        for (int m = 0; m < 15; m++) ss[m] = si2[(rbase + m)*16 + p];
        #pragma unroll
        for (int i = 0; i < 8; i++)
            #pragma unroll
            for (int j = 0; j < 8; j++)
                ffma2(acc[i], kk[j], ss[7 + i - j]);
    }

    unsigned long long* out2 = (unsigned long long*)g_syn;
    #pragma unroll
    for (int i = 0; i < 8; i++) {
        int t = t0 + ob + i;
        if (t < T_DATA) out2[(size_t)t*16 + p] = acc[i];
    }
}

// ---------------- K4: hist filter (4-way ILP) + register heap tree -> Z_out ----------------
#define TB4 288

__global__ void __launch_bounds__(TB4) k4_tree(const float* __restrict__ Z,
                                               const float* __restrict__ Theta,
                                               float* __restrict__ dout) {
    __shared__ float Zsh[TB4 + TNO];
    __shared__ float hk[TNO];
    __shared__ float Th[SUB];
    __shared__ float hw0[SUB];
    __shared__ float hw1[SUB];

    int t0  = blockIdx.x * TB4;
    int tid = threadIdx.x;

    for (int l = tid; l < TB4 + TNO; l += TB4) {
        int g = t0 - TNO + l;
        Zsh[l] = (g >= 0 && g < T_DATA) ? Z[g] : 0.f;
    }
    for (int l = tid; l < TNO; l += TB4) hk[l] = g_hk[l];
    if (tid < SUB) {
        Th[tid]  = Theta[tid];
        hw0[tid] = g_hw0[tid];
        hw1[tid] = g_hw1[tid];
    }
    __syncthreads();

    int t = t0 + tid;
    if (t >= T_DATA) return;

    float h0 = 0.f, h1 = 0.f, h2 = 0.f, h3 = 0.f;
    const float* zp = Zsh + tid + TNO - 1;
    #pragma unroll 4
    for (int tau = 0; tau < TNO; tau += 4) {
        h0 = fmaf(hk[tau+0], zp[-(tau+0)], h0);
        h1 = fmaf(hk[tau+1], zp[-(tau+1)], h1);
        h2 = fmaf(hk[tau+2], zp[-(tau+2)], h2);
        h3 = fmaf(hk[tau+3], zp[-(tau+3)], h3);
    }
    float hist = (h0 + h1) + (h2 + h3);

    float sy[SUB];
    {
        const float4* sp = (const float4*)(g_syn + (size_t)t * SUB);
        #pragma unroll
        for (int i = 0; i < 8; i++) {
            float4 v = sp[i];
            sy[i*4+0] = v.x; sy[i*4+1] = v.y; sy[i*4+2] = v.z; sy[i*4+3] = v.w;
        }
    }

    float zin;
    if (__ldg(&g_treebad) == 0) {
        float sub[SUB];
        #pragma unroll
        for (int idx = SUB - 1; idx >= 1; --idx) {
            float a = sy[idx] + Th[idx];
            if (2*idx + 1 < SUB) a = fmaf(hw0[idx], sub[2*idx + 1], a);
            if (2*idx + 2 < SUB) a = fmaf(hw1[idx], sub[2*idx + 2], a);
            sub[idx] = tanhf(a);
        }
        float leaf = fmaf(hw0[0], sub[1], fmaf(hw1[0], sub[2], 0.f));
        zin = hist + sy[0] + leaf + Th[0];
    } else {
        float subl[SUB];
        #pragma unroll
        for (int j = 0; j < SUB; j++) subl[j] = 0.f;
        for (int idx = SUB - 1; idx >= 1; --idx) {
            float a = sy[idx] + Th[idx];
            int c = g_ch_cnt[idx];
            for (int k = 0; k < c; k++)
                a = fmaf(g_ch_w[idx*SUB + k], subl[g_ch_idx[idx*SUB + k]], a);
            subl[idx] = tanhf(a);
        }
        float leaf = 0.f;
        int c = g_ch_cnt[0];
        for (int k = 0; k < c; k++)
            leaf = fmaf(g_ch_w[k], subl[g_ch_idx[k]], leaf);
        zin = hist + sy[0] + leaf + Th[0];
    }

    dout[T_DATA + t] = (zin > 0.f) ? 1.f : 0.f;
}

// ---------------- K5: output conv of Z_out (4-way ILP) -> V_out ----------------
#define TB5 288
__global__ void __launch_bounds__(TB5) k5_vout(float* __restrict__ dout) {
    __shared__ float Zsh[TB5 + TNO];
    __shared__ float ok[TNO];
    const float* zo = dout + T_DATA;

    int t0 = blockIdx.x * TB5;
    for (int l = threadIdx.x; l < TB5 + TNO; l += TB5) {
        int g = t0 - TNO + l;
        Zsh[l] = (g >= 0 && g < T_DATA) ? zo[g] : 0.f;
    }
    for (int l = threadIdx.x; l < TNO; l += TB5) ok[l] = g_ok[l];
    __syncthreads();

    int t = t0 + threadIdx.x;
    if (t >= T_DATA) return;

    float v0 = 0.f, v1 = 0.f, v2 = 0.f, v3 = 0.f;
    const float* zp = Zsh + threadIdx.x + TNO - 1;
    #pragma unroll 4
    for (int tau = 0; tau < TNO; tau += 4) {
        v0 = fmaf(ok[tau+0], zp[-(tau+0)], v0);
        v1 = fmaf(ok[tau+1], zp[-(tau+1)], v1);
        v2 = fmaf(ok[tau+2], zp[-(tau+2)], v2);
        v3 = fmaf(ok[tau+3], zp[-(tau+3)], v3);
    }
    dout[t] = (v0 + v1) + (v2 + v3);
}

// ---------------- launcher ----------------
extern "C" void kernel_launch(void* const* d_in, const int* in_sizes, int n_in,
                              void* d_out, int out_size) {
    const float* Se        = (const float*)d_in[0];
    const float* Si        = (const float*)d_in[1];
    const float* Z         = (const float*)d_in[2];
    const float* Cden      = (const float*)d_in[3];
    const float* Ce        = (const float*)d_in[4];
    const float* Ci        = (const float*)d_in[5];
    const float* Tau_syn   = (const float*)d_in[6];
    const float* Delta_syn = (const float*)d_in[7];
    const float* W_syn     = (const float*)d_in[8];
    const float* W_sub     = (const float*)d_in[9];
    const float* W_hist    = (const float*)d_in[10];
    const float* Theta     = (const float*)d_in[11];
    const float* Tau_out   = (const float*)d_in[12];
    const float* W_out     = (const float*)d_in[13];
    float* out = (float*)d_out;

    kSetup<<<512, 256>>>(Ce, Ci, Cden, W_sub, Tau_syn, Delta_syn, W_syn, W_hist,
                         Tau_out, W_out, out);
    k1_proj<<<2048, 256>>>(Se, Si);     // hot kernel

    cudaFuncSetAttribute(k3_conv, cudaFuncAttributeMaxDynamicSharedMemorySize, SMEM3);
    k3_conv<<<(T_DATA + TB3 - 1) / TB3, NT3, SMEM3>>>();   // 148 blocks = 1 wave

    k4_tree<<<(T_DATA + TB4 - 1) / TB4, TB4>>>(Z, Theta, out);  // 139 blocks

    k5_vout<<<(T_DATA + TB5 - 1) / TB5, TB5>>>(out);       // 139 blocks
}

// round 15
// speedup vs baseline: 1.0532x; 1.0532x over previous
#include <cuda_runtime.h>
#include <math.h>

#define T_DATA 40000
#define SUB    32
#define E_E    2000
#define E_I    400
#define TNO    200
#define NCOS   17
#define FILT_OFF (2*T_DATA)

#define PI_F   3.14159274f      // float32(pi), matches jnp
#define HPI_F  1.5707964f       // float32(pi/2)

// ---------------- scratch (no allocation allowed) ----------------
__device__ float g_syn_e[(size_t)T_DATA*SUB];
__device__ float g_syn_i[(size_t)T_DATA*SUB];
__device__ float g_ke[TNO*SUB];   // transposed [tau][s]
__device__ float g_ki[TNO*SUB];
__device__ float g_hk[TNO];
__device__ float g_ok[TNO];
// one-hot fast tables: {byte_offset = s*4, float_bits(w)} per column (16B-aligned)
__device__ __align__(16) int2  g_etab[E_E];
__device__ __align__(16) int2  g_itab[E_I];
__device__ int   g_multi = 0;     // sticky
// generic fallback CSR (row-major, cold)
__device__ int   g_ecnt[E_E];
__device__ int   g_esub[E_E*SUB];
__device__ float g_ew  [E_E*SUB];
__device__ int   g_icnt[E_I];
__device__ int   g_isub[E_I*SUB];
__device__ float g_iw  [E_I*SUB];
__device__ int   g_ch_cnt[SUB];
__device__ int   g_ch_idx[SUB*SUB];
__device__ float g_ch_w[SUB*SUB];
// binary-heap specialization
__device__ float g_hw0[SUB];
__device__ float g_hw1[SUB];
__device__ int   g_treebad = 0;   // sticky
// effective synaptic-kernel support (multiple of 8); sticky-max, deterministic per input
__device__ int   g_L3 = 8;

// ---------------- kSetup ----------------
__global__ void kSetup(const float* __restrict__ Ce, const float* __restrict__ Ci,
                       const float* __restrict__ C_den, const float* __restrict__ W_sub,
                       const float* __restrict__ Tau_syn, const float* __restrict__ Delta_syn,
                       const float* __restrict__ W_syn,   const float* __restrict__ W_hist,
                       const float* __restrict__ Tau_out, const float* __restrict__ W_out,
                       float* __restrict__ dout) {
    int gid = blockIdx.x * blockDim.x + threadIdx.x;
    int nth = gridDim.x * blockDim.x;

    // ---- zero atomic accumulators (every replay) ----
    float4 z4 = make_float4(0.f, 0.f, 0.f, 0.f);
    float4* ze = (float4*)g_syn_e;
    float4* zi = (float4*)g_syn_i;
    for (int i = gid; i < T_DATA*SUB/4; i += nth) { ze[i] = z4; zi[i] = z4; }

    // ---- CSR + one-hot tables ----
    if (gid < E_E) {
        int e = gid;
        int c = 0; int s0 = 0; float w0 = 0.f;
        for (int s = 0; s < SUB; s++) {
            float w = Ce[(size_t)s * E_E + e];
            if (w != 0.f) {
                if (c == 0) { s0 = s; w0 = w; }
                g_esub[e*SUB + c] = s; g_ew[e*SUB + c] = w; c++;
            }
        }
        g_ecnt[e] = c;
        g_etab[e] = make_int2(s0 * 4, __float_as_int(w0));
        if (c > 1) atomicOr(&g_multi, 1);
    }
    if (gid < E_I) {
        int e = gid;
        int c = 0; int s0 = 0; float w0 = 0.f;
        for (int s = 0; s < SUB; s++) {
            float w = Ci[(size_t)s * E_I + e];
            if (w != 0.f) {
                if (c == 0) { s0 = s; w0 = w; }
                g_isub[e*SUB + c] = s; g_iw[e*SUB + c] = w; c++;
            }
        }
        g_icnt[e] = c;
        g_itab[e] = make_int2(s0 * 4, __float_as_int(w0));
        if (c > 1) atomicOr(&g_multi, 1);
    }
    if (gid < SUB) {   // children lists + heap specialization + kernel support
        int idx = gid;
        int c = 0;
        float hw0 = 0.f, hw1 = 0.f;
        bool bad = false;
        for (int j = 0; j < SUB; j++) {
            float w = C_den[idx*SUB + j];
            if (w != 0.f) {
                float ww = w * expf(W_sub[j]);
                g_ch_idx[idx*SUB + c] = j;
                g_ch_w[idx*SUB + c]   = ww;
                c++;
                if      (j == 2*idx + 1) hw0 = ww;
                else if (j == 2*idx + 2) hw1 = ww;
                else bad = true;
            }
        }
        g_ch_cnt[idx] = c;
        g_hw0[idx] = hw0;
        g_hw1[idx] = hw1;
        if (bad) atomicOr(&g_treebad, 1);

        // effective support of this subunit's alpha kernels (suffix-sum criterion)
        {
            int s = idx;
            float de  = expf(Delta_syn[s*2 + 0]);
            float ite = 1.f / expf(Tau_syn[s*2 + 0]);
            float we  = expf(W_syn[s*2 + 0]);
            float di  = expf(Delta_syn[s*2 + 1]);
            float iti = 1.f / expf(Tau_syn[s*2 + 1]);
            float wi  = expf(W_syn[s*2 + 1]);
            float tail = 0.f;
            int L = 8;
            for (int tau = TNO - 1; tau >= 0; tau--) {
                float t = (float)tau;
                float tte = fmaxf(t - de, 0.f) * ite;
                float tti = fmaxf(t - di, 0.f) * iti;
                float ek  = tte * expf(-tte) * we;
                float ik  = tti * expf(-tti) * wi;
                tail += fabsf(ek) + fabsf(ik);
                if (tail > 1e-10f) { L = tau + 2; break; }
            }
            L = min(TNO, ((L + 7) / 8) * 8);
            atomicMax(&g_L3, L);
        }
    }

    // ---- alpha kernels + out_filters ----
    for (int i = gid; i < SUB * TNO; i += nth) {
        int s = i / TNO, tau = i % TNO;
        float t = (float)tau;
        float te  = fmaxf(t - expf(Delta_syn[s*2 + 0]), 0.f);
        float tte = te / expf(Tau_syn[s*2 + 0]);
        float ek  = tte * expf(-tte) * expf(W_syn[s*2 + 0]);
        float ti  = fmaxf(t - expf(Delta_syn[s*2 + 1]), 0.f);
        float tti = ti / expf(Tau_syn[s*2 + 1]);
        float ik  = -tti * expf(-tti) * expf(W_syn[s*2 + 1]);
        g_ke[tau*SUB + s] = ek;
        g_ki[tau*SUB + s] = ik;
        dout[FILT_OFF + s*TNO + tau]           = ek;
        dout[FILT_OFF + SUB*TNO + s*TNO + tau] = ik;
    }
    for (int tau = gid; tau < TNO; tau += nth) {
        float raw = 4.f * logf((float)tau + 1.f);
        float hk = 0.f;
        #pragma unroll
        for (int n = 0; n < NCOS; n++) {
            float phi = HPI_F * (float)n;
            if (raw >= phi - PI_F && raw <= phi + PI_F)
                hk -= expf(W_hist[n]) * (0.5f * cosf(raw - phi) + 0.5f);
        }
        g_hk[tau] = hk;
        dout[FILT_OFF + 2*SUB*TNO + tau] = hk;

        float tto = (float)tau / expf(Tau_out[0]);
        g_ok[tau] = tto * expf(-tto) * expf(W_out[0]);
    }
}

// ---------------- K1: lean predicated spike scatter (R13 winner, unguarded table loads) ----------------
__device__ __forceinline__ void spk(float v, int off, float w, float* dst) {
    asm volatile(
        "{\n\t"
        ".reg .pred p;\n\t"
        ".reg .b64 ra;\n\t"
        ".reg .f32 fv;\n\t"
        "setp.ne.f32 p, %0, 0f00000000;\n\t"
        "@p mad.wide.u32 ra, %1, 1, %3;\n\t"
        "@p mul.f32 fv, %0, %2;\n\t"
        "@p red.global.add.f32 [ra], fv;\n\t"
        "}" :: "f"(v), "r"((unsigned)off), "f"(w), "l"(dst));
}

__device__ __forceinline__ void proc_e(float4 v, int q) {
    unsigned t = (unsigned)q / 500u;
    int e0 = (q - (int)t * 500) * 4;
    float* dst = g_syn_e + (size_t)t * SUB;
    const int4* tb = (const int4*)(g_etab + e0);
    int4 p0 = __ldg(tb);       // {off0, w0, off1, w1}
    int4 p1 = __ldg(tb + 1);   // {off2, w2, off3, w3}
    spk(v.x, p0.x, __int_as_float(p0.y), dst);
    spk(v.y, p0.z, __int_as_float(p0.w), dst);
    spk(v.z, p1.x, __int_as_float(p1.y), dst);
    spk(v.w, p1.z, __int_as_float(p1.w), dst);
}
__device__ __forceinline__ void proc_i(float4 v, int q) {
    unsigned t = (unsigned)q / 100u;
    int e0 = (q - (int)t * 100) * 4;
    float* dst = g_syn_i + (size_t)t * SUB;
    const int4* tb = (const int4*)(g_itab + e0);
    int4 p0 = __ldg(tb);
    int4 p1 = __ldg(tb + 1);
    spk(v.x, p0.x, __int_as_float(p0.y), dst);
    spk(v.y, p0.z, __int_as_float(p0.w), dst);
    spk(v.z, p1.x, __int_as_float(p1.y), dst);
    spk(v.w, p1.z, __int_as_float(p1.w), dst);
}

__global__ void __launch_bounds__(256, 3) k1_proj(const float* __restrict__ Se,
                                                  const float* __restrict__ Si) {
    int gt  = blockIdx.x * blockDim.x + threadIdx.x;
    int nth = gridDim.x * blockDim.x;

    {
        const float4* p = (const float4*)Se;
        const int H = T_DATA * (E_E/4) / 2;     // 10,000,000
        int q = gt;
        if (q < H) {
            float4 a0 = __ldcs(p + q);
            float4 b0 = __ldcs(p + q + H);
            for (;;) {
                int q2 = q + nth;
                bool have = q2 < H;
                float4 a1, b1;
                if (have) { a1 = __ldcs(p + q2); b1 = __ldcs(p + q2 + H); }
                proc_e(a0, q);
                proc_e(b0, q + H);
                if (!have) break;
                a0 = a1; b0 = b1; q = q2;
            }
        }
    }
    {
        const float4* p = (const float4*)Si;
        const int H = T_DATA * (E_I/4) / 2;     // 2,000,000
        int q = gt;
        if (q < H) {
            float4 a0 = __ldcs(p + q);
            float4 b0 = __ldcs(p + q + H);
            for (;;) {
                int q2 = q + nth;
                bool have = q2 < H;
                float4 a1, b1;
                if (have) { a1 = __ldcs(p + q2); b1 = __ldcs(p + q2 + H); }
                proc_i(a0, q);
                proc_i(b0, q + H);
                if (!have) break;
                a0 = a1; b0 = b1; q = q2;
            }
        }
    }

    // ---- generic fallback for non-one-hot columns (never taken for this data) ----
    if (__ldg(&g_multi) != 0) {
        for (int e = gt; e < E_E; e += nth) {
            int c = g_ecnt[e];
            if (c > 1) {
                for (int t = 0; t < T_DATA; t++) {
                    float v = Se[(size_t)t * E_E + e];
                    if (v != 0.f)
                        for (int k = 1; k < c; k++)
                            atomicAdd(g_syn_e + (size_t)t*SUB + g_esub[e*SUB+k], v * g_ew[e*SUB+k]);
                }
            }
        }
        for (int e = gt; e < E_I; e += nth) {
            int c = g_icnt[e];
            if (c > 1) {
                for (int t = 0; t < T_DATA; t++) {
                    float v = Si[(size_t)t * E_I + e];
                    if (v != 0.f)
                        for (int k = 1; k < c; k++)
                            atomicAdd(g_syn_i + (size_t)t*SUB + g_isub[e*SUB+k], v * g_iw[e*SUB+k]);
                }
            }
        }
    }
}

// ---------------- K34: depthwise conv (truncated) FUSED with hist + tree + heaviside ----------------
__device__ __forceinline__ void ffma2(unsigned long long& d,
                                      unsigned long long a, unsigned long long b) {
    asm("fma.rn.f32x2 %0, %1, %2, %0;" : "+l"(d) : "l"(a), "l"(b));
}

#define TB3   272
#define NT3   544
#define ROWS3 (TB3 + TNO)                      // 472
#define SYNPAD 33
// floats: se 472*32 + si 472*32 + syn 272*33 + Z 472 + hk 200 + Th/hw0/hw1 96
#define SMEM34 ((ROWS3*SUB*2 + TB3*SYNPAD + ROWS3 + TNO + 3*SUB) * (int)sizeof(float))

__global__ void __launch_bounds__(NT3) k34_conv_tree(const float* __restrict__ Z,
                                                     const float* __restrict__ Theta,
                                                     float* __restrict__ dout) {
    extern __shared__ float sh[];
    float* se_sh  = sh;                         // [ROWS3][32]
    float* si_sh  = se_sh + ROWS3 * SUB;        // [ROWS3][32]
    float* syn_sh = si_sh + ROWS3 * SUB;        // [TB3][33] padded
    float* Zsh    = syn_sh + TB3 * SYNPAD;      // [ROWS3]
    float* hk     = Zsh + ROWS3;                // [TNO]
    float* Th     = hk + TNO;                   // [SUB]
    float* hw0    = Th + SUB;                   // [SUB]
    float* hw1    = hw0 + SUB;                  // [SUB]

    int t0  = blockIdx.x * TB3;
    int tid = threadIdx.x;
    int L   = g_L3;
    if (L > TNO) L = TNO;
    int row0 = TNO - L;

    // ---- stage tiles + Z window + small tables ----
    {
        const float4* ge = (const float4*)g_syn_e;
        const float4* gi = (const float4*)g_syn_i;
        float4* de = (float4*)se_sh;
        float4* di = (float4*)si_sh;
        float4 z = make_float4(0.f, 0.f, 0.f, 0.f);
        for (int l = tid + row0 * 8; l < ROWS3 * 8; l += NT3) {
            int row = l >> 3, c = l & 7;
            int g = t0 - TNO + row;
            if (g >= 0 && g < T_DATA) { de[l] = ge[g*8 + c]; di[l] = gi[g*8 + c]; }
            else                      { de[l] = z;           di[l] = z;           }
        }
        for (int l = tid; l < ROWS3; l += NT3) {
            int g = t0 - TNO + l;
            Zsh[l] = (g >= 0 && g < T_DATA) ? Z[g] : 0.f;
        }
        for (int l = tid; l < TNO; l += NT3) hk[l] = g_hk[l];
        if (tid < SUB) {
            Th[tid]  = Theta[tid];
            hw0[tid] = g_hw0[tid];
            hw1[tid] = g_hw1[tid];
        }
    }
    __syncthreads();

    int lane  = tid & 31, wid = tid >> 5;
    int p     = lane & 15;
    int tslot = lane >> 4;
    int ob    = wid * 16 + tslot * 8;

    const unsigned long long* se2 = (const unsigned long long*)se_sh;
    const unsigned long long* si2 = (const unsigned long long*)si_sh;
    const unsigned long long* ke2 = (const unsigned long long*)g_ke;
    const unsigned long long* ki2 = (const unsigned long long*)g_ki;

    unsigned long long acc[8];
    #pragma unroll
    for (int i = 0; i < 8; i++) acc[i] = 0ull;

    for (int tb = 0; tb < L; tb += 8) {
        int rbase = ob + 192 - tb;
        unsigned long long kk[8], ss[15];

        #pragma unroll
        for (int j = 0; j < 8; j++) kk[j] = __ldg(&ke2[(tb + j)*16 + p]);
        #pragma unroll
        for (int m = 0; m < 15; m++) ss[m] = se2[(rbase + m)*16 + p];
        #pragma unroll
        for (int i = 0; i < 8; i++)
            #pragma unroll
            for (int j = 0; j < 8; j++)
                ffma2(acc[i], kk[j], ss[7 + i - j]);

        #pragma unroll
        for (int j = 0; j < 8; j++) kk[j] = __ldg(&ki2[(tb + j)*16 + p]);
        #pragma unroll
        for (int m = 0; m < 15; m++) ss[m] = si2[(rbase + m)*16 + p];
        #pragma unroll
        for (int i = 0; i < 8; i++)
            #pragma unroll
            for (int j = 0; j < 8; j++)
                ffma2(acc[i], kk[j], ss[7 + i - j]);
    }

    // ---- deposit syn into padded smem (conflict-free columns for the tree walk) ----
    #pragma unroll
    for (int i = 0; i < 8; i++) {
        float lo = __uint_as_float((unsigned)(acc[i] & 0xffffffffull));
        float hi = __uint_as_float((unsigned)(acc[i] >> 32));
        syn_sh[(ob + i) * SYNPAD + 2*p + 0] = lo;
        syn_sh[(ob + i) * SYNPAD + 2*p + 1] = hi;
    }
    __syncthreads();

    // ---- epilogue: threads 0..271 do hist conv + tree walk + heaviside ----
    if (tid < TB3) {
        int t = t0 + tid;
        if (t < T_DATA) {
            float h0 = 0.f, h1 = 0.f, h2 = 0.f, h3 = 0.f;
            const float* zp = Zsh + tid + TNO - 1;
            #pragma unroll 4
            for (int tau = 0; tau < TNO; tau += 4) {
                h0 = fmaf(hk[tau+0], zp[-(tau+0)], h0);
                h1 = fmaf(hk[tau+1], zp[-(tau+1)], h1);
                h2 = fmaf(hk[tau+2], zp[-(tau+2)], h2);
                h3 = fmaf(hk[tau+3], zp[-(tau+3)], h3);
            }
            float hist = (h0 + h1) + (h2 + h3);

            const float* sy = syn_sh + tid * SYNPAD;
            float zin;
            if (__ldg(&g_treebad) == 0) {
                float sub[SUB];
                #pragma unroll
                for (int idx = SUB - 1; idx >= 1; --idx) {
                    float a = sy[idx] + Th[idx];
                    if (2*idx + 1 < SUB) a = fmaf(hw0[idx], sub[2*idx + 1], a);
                    if (2*idx + 2 < SUB) a = fmaf(hw1[idx], sub[2*idx + 2], a);
                    sub[idx] = tanhf(a);
                }
                float leaf = fmaf(hw0[0], sub[1], fmaf(hw1[0], sub[2], 0.f));
                zin = hist + sy[0] + leaf + Th[0];
            } else {
                float subl[SUB];
                #pragma unroll
                for (int j = 0; j < SUB; j++) subl[j] = 0.f;
                for (int idx = SUB - 1; idx >= 1; --idx) {
                    float a = sy[idx] + Th[idx];
                    int c = g_ch_cnt[idx];
                    for (int k = 0; k < c; k++)
                        a = fmaf(g_ch_w[idx*SUB + k], subl[g_ch_idx[idx*SUB + k]], a);
                    subl[idx] = tanhf(a);
                }
                float leaf = 0.f;
                int c = g_ch_cnt[0];
                for (int k = 0; k < c; k++)
                    leaf = fmaf(g_ch_w[k], subl[g_ch_idx[k]], leaf);
                zin = hist + sy[0] + leaf + Th[0];
            }

            dout[T_DATA + t] = (zin > 0.f) ? 1.f : 0.f;
        }
    }
}

// ---------------- K5: output conv of Z_out (4-way ILP) -> V_out ----------------
#define TB5 288
__global__ void __launch_bounds__(TB5) k5_vout(float* __restrict__ dout) {
    __shared__ float Zsh[TB5 + TNO];
    __shared__ float ok[TNO];
    const float* zo = dout + T_DATA;

    int t0 = blockIdx.x * TB5;
    for (int l = threadIdx.x; l < TB5 + TNO; l += TB5) {
        int g = t0 - TNO + l;
        Zsh[l] = (g >= 0 && g < T_DATA) ? zo[g] : 0.f;
    }
    for (int l = threadIdx.x; l < TNO; l += TB5) ok[l] = g_ok[l];
    __syncthreads();

    int t = t0 + threadIdx.x;
    if (t >= T_DATA) return;

    float v0 = 0.f, v1 = 0.f, v2 = 0.f, v3 = 0.f;
    const float* zp = Zsh + threadIdx.x + TNO - 1;
    #pragma unroll 4
    for (int tau = 0; tau < TNO; tau += 4) {
        v0 = fmaf(ok[tau+0], zp[-(tau+0)], v0);
        v1 = fmaf(ok[tau+1], zp[-(tau+1)], v1);
        v2 = fmaf(ok[tau+2], zp[-(tau+2)], v2);
        v3 = fmaf(ok[tau+3], zp[-(tau+3)], v3);
    }
    dout[t] = (v0 + v1) + (v2 + v3);
}

// ---------------- launcher ----------------
extern "C" void kernel_launch(void* const* d_in, const int* in_sizes, int n_in,
                              void* d_out, int out_size) {
    const float* Se        = (const float*)d_in[0];
    const float* Si        = (const float*)d_in[1];
    const float* Z         = (const float*)d_in[2];
    const float* Cden      = (const float*)d_in[3];
    const float* Ce        = (const float*)d_in[4];
    const float* Ci        = (const float*)d_in[5];
    const float* Tau_syn   = (const float*)d_in[6];
    const float* Delta_syn = (const float*)d_in[7];
    const float* W_syn     = (const float*)d_in[8];
    const float* W_sub     = (const float*)d_in[9];
    const float* W_hist    = (const float*)d_in[10];
    const float* Theta     = (const float*)d_in[11];
    const float* Tau_out   = (const float*)d_in[12];
    const float* W_out     = (const float*)d_in[13];
    float* out = (float*)d_out;

    kSetup<<<512, 256>>>(Ce, Ci, Cden, W_sub, Tau_syn, Delta_syn, W_syn, W_hist,
                         Tau_out, W_out, out);
    k1_proj<<<2048, 256>>>(Se, Si);     // hot kernel

    cudaFuncSetAttribute(k34_conv_tree, cudaFuncAttributeMaxDynamicSharedMemorySize, SMEM34);
    k34_conv_tree<<<(T_DATA + TB3 - 1) / TB3, NT3, SMEM34>>>(Z, Theta, out);  // 148 blocks

    k5_vout<<<(T_DATA + TB5 - 1) / TB5, TB5>>>(out);       // 139 blocks
}

// round 16
// speedup vs baseline: 1.2836x; 1.2187x over previous
#include <cuda_runtime.h>
#include <math.h>

#define T_DATA 40000
#define SUB    32
#define E_E    2000
#define E_I    400
#define TNO    200
#define NCOS   17
#define FILT_OFF (2*T_DATA)

#define PI_F   3.14159274f      // float32(pi), matches jnp
#define HPI_F  1.5707964f       // float32(pi/2)

// ---------------- scratch (no allocation allowed) ----------------
__device__ float g_syn_e[(size_t)T_DATA*SUB];
__device__ float g_syn_i[(size_t)T_DATA*SUB];
__device__ float g_ke[TNO*SUB];   // transposed [tau][s]
__device__ float g_ki[TNO*SUB];
__device__ float g_hk[TNO];
__device__ float g_ok[TNO];
// one-hot fast tables: {byte_offset = s*4, float_bits(w)} per column (16B-aligned)
__device__ __align__(16) int2  g_etab[E_E];
__device__ __align__(16) int2  g_itab[E_I];
__device__ int   g_multi = 0;     // sticky
// generic fallback CSR (row-major, cold)
__device__ int   g_ecnt[E_E];
__device__ int   g_esub[E_E*SUB];
__device__ float g_ew  [E_E*SUB];
__device__ int   g_icnt[E_I];
__device__ int   g_isub[E_I*SUB];
__device__ float g_iw  [E_I*SUB];
__device__ int   g_ch_cnt[SUB];
__device__ int   g_ch_idx[SUB*SUB];
__device__ float g_ch_w[SUB*SUB];
// binary-heap specialization
__device__ float g_hw0[SUB];
__device__ float g_hw1[SUB];
__device__ int   g_treebad = 0;   // sticky
// effective synaptic-kernel support (multiple of 8); sticky-max, deterministic per input
__device__ int   g_L3 = 8;

// ---------------- kSetup ----------------
__global__ void kSetup(const float* __restrict__ Ce, const float* __restrict__ Ci,
                       const float* __restrict__ C_den, const float* __restrict__ W_sub,
                       const float* __restrict__ Tau_syn, const float* __restrict__ Delta_syn,
                       const float* __restrict__ W_syn,   const float* __restrict__ W_hist,
                       const float* __restrict__ Tau_out, const float* __restrict__ W_out,
                       float* __restrict__ dout) {
    int gid = blockIdx.x * blockDim.x + threadIdx.x;
    int nth = gridDim.x * blockDim.x;

    // ---- zero atomic accumulators (every replay) ----
    float4 z4 = make_float4(0.f, 0.f, 0.f, 0.f);
    float4* ze = (float4*)g_syn_e;
    float4* zi = (float4*)g_syn_i;
    for (int i = gid; i < T_DATA*SUB/4; i += nth) { ze[i] = z4; zi[i] = z4; }

    // ---- CSR + one-hot tables ----
    if (gid < E_E) {
        int e = gid;
        int c = 0; int s0 = 0; float w0 = 0.f;
        for (int s = 0; s < SUB; s++) {
            float w = Ce[(size_t)s * E_E + e];
            if (w != 0.f) {
                if (c == 0) { s0 = s; w0 = w; }
                g_esub[e*SUB + c] = s; g_ew[e*SUB + c] = w; c++;
            }
        }
        g_ecnt[e] = c;
        g_etab[e] = make_int2(s0 * 4, __float_as_int(w0));
        if (c > 1) atomicOr(&g_multi, 1);
    }
    if (gid < E_I) {
        int e = gid;
        int c = 0; int s0 = 0; float w0 = 0.f;
        for (int s = 0; s < SUB; s++) {
            float w = Ci[(size_t)s * E_I + e];
            if (w != 0.f) {
                if (c == 0) { s0 = s; w0 = w; }
                g_isub[e*SUB + c] = s; g_iw[e*SUB + c] = w; c++;
            }
        }
        g_icnt[e] = c;
        g_itab[e] = make_int2(s0 * 4, __float_as_int(w0));
        if (c > 1) atomicOr(&g_multi, 1);
    }
    if (gid < SUB) {   // children lists + heap specialization + kernel support
        int idx = gid;
        int c = 0;
        float hw0 = 0.f, hw1 = 0.f;
        bool bad = false;
        for (int j = 0; j < SUB; j++) {
            float w = C_den[idx*SUB + j];
            if (w != 0.f) {
                float ww = w * expf(W_sub[j]);
                g_ch_idx[idx*SUB + c] = j;
                g_ch_w[idx*SUB + c]   = ww;
                c++;
                if      (j == 2*idx + 1) hw0 = ww;
                else if (j == 2*idx + 2) hw1 = ww;
                else bad = true;
            }
        }
        g_ch_cnt[idx] = c;
        g_hw0[idx] = hw0;
        g_hw1[idx] = hw1;
        if (bad) atomicOr(&g_treebad, 1);

        // effective support of this subunit's alpha kernels (suffix-sum criterion)
        {
            int s = idx;
            float de  = expf(Delta_syn[s*2 + 0]);
            float ite = 1.f / expf(Tau_syn[s*2 + 0]);
            float we  = expf(W_syn[s*2 + 0]);
            float di  = expf(Delta_syn[s*2 + 1]);
            float iti = 1.f / expf(Tau_syn[s*2 + 1]);
            float wi  = expf(W_syn[s*2 + 1]);
            float tail = 0.f;
            int L = 8;
            for (int tau = TNO - 1; tau >= 0; tau--) {
                float t = (float)tau;
                float tte = fmaxf(t - de, 0.f) * ite;
                float tti = fmaxf(t - di, 0.f) * iti;
                float ek  = tte * expf(-tte) * we;
                float ik  = tti * expf(-tti) * wi;
                tail += fabsf(ek) + fabsf(ik);
                if (tail > 1e-10f) { L = tau + 2; break; }
            }
            L = min(TNO, ((L + 7) / 8) * 8);
            atomicMax(&g_L3, L);
        }
    }

    // ---- alpha kernels + out_filters ----
    for (int i = gid; i < SUB * TNO; i += nth) {
        int s = i / TNO, tau = i % TNO;
        float t = (float)tau;
        float te  = fmaxf(t - expf(Delta_syn[s*2 + 0]), 0.f);
        float tte = te / expf(Tau_syn[s*2 + 0]);
        float ek  = tte * expf(-tte) * expf(W_syn[s*2 + 0]);
        float ti  = fmaxf(t - expf(Delta_syn[s*2 + 1]), 0.f);
        float tti = ti / expf(Tau_syn[s*2 + 1]);
        float ik  = -tti * expf(-tti) * expf(W_syn[s*2 + 1]);
        g_ke[tau*SUB + s] = ek;
        g_ki[tau*SUB + s] = ik;
        dout[FILT_OFF + s*TNO + tau]           = ek;
        dout[FILT_OFF + SUB*TNO + s*TNO + tau] = ik;
    }
    for (int tau = gid; tau < TNO; tau += nth) {
        float raw = 4.f * logf((float)tau + 1.f);
        float hk = 0.f;
        #pragma unroll
        for (int n = 0; n < NCOS; n++) {
            float phi = HPI_F * (float)n;
            if (raw >= phi - PI_F && raw <= phi + PI_F)
                hk -= expf(W_hist[n]) * (0.5f * cosf(raw - phi) + 0.5f);
        }
        g_hk[tau] = hk;
        dout[FILT_OFF + 2*SUB*TNO + tau] = hk;

        float tto = (float)tau / expf(Tau_out[0]);
        g_ok[tau] = tto * expf(-tto) * expf(W_out[0]);
    }
}

// ---------------- K1: residue-invariant scatter (tables & pointers loop-hoisted) ----------------
#define NB1  2000
#define NTH1 (NB1 * 256)          // 512000: multiple of 500 and 100

// 3-slot scatter: setp / mul / red [ptr + IMM]
template<int IMM>
__device__ __forceinline__ void spk3(float v, float w, unsigned long long ptr) {
    asm volatile(
        "{\n\t"
        ".reg .pred p;\n\t"
        ".reg .f32 fv;\n\t"
        "setp.ne.f32 p, %0, 0f00000000;\n\t"
        "@p mul.f32 fv, %0, %1;\n\t"
        "@p red.global.add.f32 [%2+%3], fv;\n\t"
        "}" :: "f"(v), "f"(w), "l"(ptr), "n"(IMM));
}

__global__ void __launch_bounds__(256, 3) k1_proj(const float* __restrict__ Se,
                                                  const float* __restrict__ Si) {
    int gt = blockIdx.x * blockDim.x + threadIdx.x;

    // ---- excitatory: rows of 500 quads; NTH1/500 = 1024 rows per stride ----
    {
        const float4* p = (const float4*)Se;
        const int H = T_DATA * (E_E/4) / 2;       // 10,000,000 quads per half
        unsigned t0 = (unsigned)gt / 500u;
        int e0 = (gt - (int)t0 * 500) * 4;
        const int4* tb = (const int4*)(g_etab + e0);
        int4 q0 = __ldg(tb), q1 = __ldg(tb + 1);
        char* base = (char*)g_syn_e + (size_t)t0 * (SUB*4);
        unsigned long long pt0 = (unsigned long long)(base + q0.x);
        unsigned long long pt1 = (unsigned long long)(base + q0.z);
        unsigned long long pt2 = (unsigned long long)(base + q1.x);
        unsigned long long pt3 = (unsigned long long)(base + q1.z);
        float w0 = __int_as_float(q0.y), w1 = __int_as_float(q0.w);
        float w2 = __int_as_float(q1.y), w3 = __int_as_float(q1.w);

        int q = gt;
        float4 a0 = __ldcs(p + q);
        float4 b0 = __ldcs(p + q + H);
        for (;;) {
            int q2 = q + NTH1;
            bool have = q2 < H;
            float4 a1, b1;
            if (have) { a1 = __ldcs(p + q2); b1 = __ldcs(p + q2 + H); }
            spk3<0>(a0.x, w0, pt0);
            spk3<0>(a0.y, w1, pt1);
            spk3<0>(a0.z, w2, pt2);
            spk3<0>(a0.w, w3, pt3);
            spk3<2560000>(b0.x, w0, pt0);   // +20000 rows * 128 B
            spk3<2560000>(b0.y, w1, pt1);
            spk3<2560000>(b0.z, w2, pt2);
            spk3<2560000>(b0.w, w3, pt3);
            if (!have) break;
            a0 = a1; b0 = b1; q = q2;
            pt0 += 131072; pt1 += 131072; pt2 += 131072; pt3 += 131072;  // +1024 rows
        }
    }
    // ---- inhibitory: rows of 100 quads; NTH1/100 = 5120 rows per stride ----
    {
        const float4* p = (const float4*)Si;
        const int H = T_DATA * (E_I/4) / 2;       // 2,000,000 quads per half
        unsigned t0 = (unsigned)gt / 100u;
        int e0 = (gt - (int)t0 * 100) * 4;
        const int4* tb = (const int4*)(g_itab + e0);
        int4 q0 = __ldg(tb), q1 = __ldg(tb + 1);
        char* base = (char*)g_syn_i + (size_t)t0 * (SUB*4);
        unsigned long long pt0 = (unsigned long long)(base + q0.x);
        unsigned long long pt1 = (unsigned long long)(base + q0.z);
        unsigned long long pt2 = (unsigned long long)(base + q1.x);
        unsigned long long pt3 = (unsigned long long)(base + q1.z);
        float w0 = __int_as_float(q0.y), w1 = __int_as_float(q0.w);
        float w2 = __int_as_float(q1.y), w3 = __int_as_float(q1.w);

        int q = gt;
        float4 a0 = __ldcs(p + q);
        float4 b0 = __ldcs(p + q + H);
        for (;;) {
            int q2 = q + NTH1;
            bool have = q2 < H;
            float4 a1, b1;
            if (have) { a1 = __ldcs(p + q2); b1 = __ldcs(p + q2 + H); }
            spk3<0>(a0.x, w0, pt0);
            spk3<0>(a0.y, w1, pt1);
            spk3<0>(a0.z, w2, pt2);
            spk3<0>(a0.w, w3, pt3);
            spk3<2560000>(b0.x, w0, pt0);   // +20000 rows * 128 B
            spk3<2560000>(b0.y, w1, pt1);
            spk3<2560000>(b0.z, w2, pt2);
            spk3<2560000>(b0.w, w3, pt3);
            if (!have) break;
            a0 = a1; b0 = b1; q = q2;
            pt0 += 655360; pt1 += 655360; pt2 += 655360; pt3 += 655360;  // +5120 rows
        }
    }

    // ---- generic fallback for non-one-hot columns (never taken for this data) ----
    if (__ldg(&g_multi) != 0) {
        int nth = gridDim.x * blockDim.x;
        for (int e = gt; e < E_E; e += nth) {
            int c = g_ecnt[e];
            if (c > 1) {
                for (int t = 0; t < T_DATA; t++) {
                    float v = Se[(size_t)t * E_E + e];
                    if (v != 0.f)
                        for (int k = 1; k < c; k++)
                            atomicAdd(g_syn_e + (size_t)t*SUB + g_esub[e*SUB+k], v * g_ew[e*SUB+k]);
                }
            }
        }
        for (int e = gt; e < E_I; e += nth) {
            int c = g_icnt[e];
            if (c > 1) {
                for (int t = 0; t < T_DATA; t++) {
                    float v = Si[(size_t)t * E_I + e];
                    if (v != 0.f)
                        for (int k = 1; k < c; k++)
                            atomicAdd(g_syn_i + (size_t)t*SUB + g_isub[e*SUB+k], v * g_iw[e*SUB+k]);
                }
            }
        }
    }
}

// ---------------- K34: depthwise conv (truncated) FUSED with hist + tree + heaviside ----------------
__device__ __forceinline__ void ffma2(unsigned long long& d,
                                      unsigned long long a, unsigned long long b) {
    asm("fma.rn.f32x2 %0, %1, %2, %0;" : "+l"(d) : "l"(a), "l"(b));
}

#define TB3   272
#define NT3   544
#define ROWS3 (TB3 + TNO)                      // 472
#define SYNPAD 33
#define SMEM34 ((ROWS3*SUB*2 + TB3*SYNPAD + ROWS3 + TNO + 3*SUB) * (int)sizeof(float))

__global__ void __launch_bounds__(NT3) k34_conv_tree(const float* __restrict__ Z,
                                                     const float* __restrict__ Theta,
                                                     float* __restrict__ dout) {
    extern __shared__ float sh[];
    float* se_sh  = sh;                         // [ROWS3][32]
    float* si_sh  = se_sh + ROWS3 * SUB;        // [ROWS3][32]
    float* syn_sh = si_sh + ROWS3 * SUB;        // [TB3][33] padded
    float* Zsh    = syn_sh + TB3 * SYNPAD;      // [ROWS3]
    float* hk     = Zsh + ROWS3;                // [TNO]
    float* Th     = hk + TNO;                   // [SUB]
    float* hw0    = Th + SUB;                   // [SUB]
    float* hw1    = hw0 + SUB;                  // [SUB]

    int t0  = blockIdx.x * TB3;
    int tid = threadIdx.x;
    int L   = g_L3;
    if (L > TNO) L = TNO;
    int row0 = TNO - L;

    {
        const float4* ge = (const float4*)g_syn_e;
        const float4* gi = (const float4*)g_syn_i;
        float4* de = (float4*)se_sh;
        float4* di = (float4*)si_sh;
        float4 z = make_float4(0.f, 0.f, 0.f, 0.f);
        for (int l = tid + row0 * 8; l < ROWS3 * 8; l += NT3) {
            int row = l >> 3, c = l & 7;
            int g = t0 - TNO + row;
            if (g >= 0 && g < T_DATA) { de[l] = ge[g*8 + c]; di[l] = gi[g*8 + c]; }
            else                      { de[l] = z;           di[l] = z;           }
        }
        for (int l = tid; l < ROWS3; l += NT3) {
            int g = t0 - TNO + l;
            Zsh[l] = (g >= 0 && g < T_DATA) ? Z[g] : 0.f;
        }
        for (int l = tid; l < TNO; l += NT3) hk[l] = g_hk[l];
        if (tid < SUB) {
            Th[tid]  = Theta[tid];
            hw0[tid] = g_hw0[tid];
            hw1[tid] = g_hw1[tid];
        }
    }
    __syncthreads();

    int lane  = tid & 31, wid = tid >> 5;
    int p     = lane & 15;
    int tslot = lane >> 4;
    int ob    = wid * 16 + tslot * 8;

    const unsigned long long* se2 = (const unsigned long long*)se_sh;
    const unsigned long long* si2 = (const unsigned long long*)si_sh;
    const unsigned long long* ke2 = (const unsigned long long*)g_ke;
    const unsigned long long* ki2 = (const unsigned long long*)g_ki;

    unsigned long long acc[8];
    #pragma unroll
    for (int i = 0; i < 8; i++) acc[i] = 0ull;

    for (int tb = 0; tb < L; tb += 8) {
        int rbase = ob + 192 - tb;
        unsigned long long kk[8], ss[15];

        #pragma unroll
        for (int j = 0; j < 8; j++) kk[j] = __ldg(&ke2[(tb + j)*16 + p]);
        #pragma unroll
        for (int m = 0; m < 15; m++) ss[m] = se2[(rbase + m)*16 + p];
        #pragma unroll
        for (int i = 0; i < 8; i++)
            #pragma unroll
            for (int j = 0; j < 8; j++)
                ffma2(acc[i], kk[j], ss[7 + i - j]);

        #pragma unroll
        for (int j = 0; j < 8; j++) kk[j] = __ldg(&ki2[(tb + j)*16 + p]);
        #pragma unroll
        for (int m = 0; m < 15; m++) ss[m] = si2[(rbase + m)*16 + p];
        #pragma unroll
        for (int i = 0; i < 8; i++)
            #pragma unroll
            for (int j = 0; j < 8; j++)
                ffma2(acc[i], kk[j], ss[7 + i - j]);
    }

    #pragma unroll
    for (int i = 0; i < 8; i++) {
        float lo = __uint_as_float((unsigned)(acc[i] & 0xffffffffull));
        float hi = __uint_as_float((unsigned)(acc[i] >> 32));
        syn_sh[(ob + i) * SYNPAD + 2*p + 0] = lo;
        syn_sh[(ob + i) * SYNPAD + 2*p + 1] = hi;
    }
    __syncthreads();

    if (tid < TB3) {
        int t = t0 + tid;
        if (t < T_DATA) {
            float h0 = 0.f, h1 = 0.f, h2 = 0.f, h3 = 0.f;
            const float* zp = Zsh + tid + TNO - 1;
            #pragma unroll 4
            for (int tau = 0; tau < TNO; tau += 4) {
                h0 = fmaf(hk[tau+0], zp[-(tau+0)], h0);
                h1 = fmaf(hk[tau+1], zp[-(tau+1)], h1);
                h2 = fmaf(hk[tau+2], zp[-(tau+2)], h2);
                h3 = fmaf(hk[tau+3], zp[-(tau+3)], h3);
            }
            float hist = (h0 + h1) + (h2 + h3);

            const float* sy = syn_sh + tid * SYNPAD;
            float zin;
            if (__ldg(&g_treebad) == 0) {
                float sub[SUB];
                #pragma unroll
                for (int idx = SUB - 1; idx >= 1; --idx) {
                    float a = sy[idx] + Th[idx];
                    if (2*idx + 1 < SUB) a = fmaf(hw0[idx], sub[2*idx + 1], a);
                    if (2*idx + 2 < SUB) a = fmaf(hw1[idx], sub[2*idx + 2], a);
                    sub[idx] = tanhf(a);
                }
                float leaf = fmaf(hw0[0], sub[1], fmaf(hw1[0], sub[2], 0.f));
                zin = hist + sy[0] + leaf + Th[0];
            } else {
                float subl[SUB];
                #pragma unroll
                for (int j = 0; j < SUB; j++) subl[j] = 0.f;
                for (int idx = SUB - 1; idx >= 1; --idx) {
                    float a = sy[idx] + Th[idx];
                    int c = g_ch_cnt[idx];
                    for (int k = 0; k < c; k++)
                        a = fmaf(g_ch_w[idx*SUB + k], subl[g_ch_idx[idx*SUB + k]], a);
                    subl[idx] = tanhf(a);
                }
                float leaf = 0.f;
                int c = g_ch_cnt[0];
                for (int k = 0; k < c; k++)
                    leaf = fmaf(g_ch_w[k], subl[g_ch_idx[k]], leaf);
                zin = hist + sy[0] + leaf + Th[0];
            }

            dout[T_DATA + t] = (zin > 0.f) ? 1.f : 0.f;
        }
    }
}

// ---------------- K5: output conv of Z_out (4-way ILP) -> V_out ----------------
#define TB5 288
__global__ void __launch_bounds__(TB5) k5_vout(float* __restrict__ dout) {
    __shared__ float Zsh[TB5 + TNO];
    __shared__ float ok[TNO];
    const float* zo = dout + T_DATA;

    int t0 = blockIdx.x * TB5;
    for (int l = threadIdx.x; l < TB5 + TNO; l += TB5) {
        int g = t0 - TNO + l;
        Zsh[l] = (g >= 0 && g < T_DATA) ? zo[g] : 0.f;
    }
    for (int l = threadIdx.x; l < TNO; l += TB5) ok[l] = g_ok[l];
    __syncthreads();

    int t = t0 + threadIdx.x;
    if (t >= T_DATA) return;

    float v0 = 0.f, v1 = 0.f, v2 = 0.f, v3 = 0.f;
    const float* zp = Zsh + threadIdx.x + TNO - 1;
    #pragma unroll 4
    for (int tau = 0; tau < TNO; tau += 4) {
        v0 = fmaf(ok[tau+0], zp[-(tau+0)], v0);
        v1 = fmaf(ok[tau+1], zp[-(tau+1)], v1);
        v2 = fmaf(ok[tau+2], zp[-(tau+2)], v2);
        v3 = fmaf(ok[tau+3], zp[-(tau+3)], v3);
    }
    dout[t] = (v0 + v1) + (v2 + v3);
}

// ---------------- launcher ----------------
extern "C" void kernel_launch(void* const* d_in, const int* in_sizes, int n_in,
                              void* d_out, int out_size) {
    const float* Se        = (const float*)d_in[0];
    const float* Si        = (const float*)d_in[1];
    const float* Z         = (const float*)d_in[2];
    const float* Cden      = (const float*)d_in[3];
    const float* Ce        = (const float*)d_in[4];
    const float* Ci        = (const float*)d_in[5];
    const float* Tau_syn   = (const float*)d_in[6];
    const float* Delta_syn = (const float*)d_in[7];
    const float* W_syn     = (const float*)d_in[8];
    const float* W_sub     = (const float*)d_in[9];
    const float* W_hist    = (const float*)d_in[10];
    const float* Theta     = (const float*)d_in[11];
    const float* Tau_out   = (const float*)d_in[12];
    const float* W_out     = (const float*)d_in[13];
    float* out = (float*)d_out;

    kSetup<<<512, 256>>>(Ce, Ci, Cden, W_sub, Tau_syn, Delta_syn, W_syn, W_hist,
                         Tau_out, W_out, out);
    k1_proj<<<NB1, 256>>>(Se, Si);      // 2000 blocks: NTH1 divides 500 & 100 rows

    cudaFuncSetAttribute(k34_conv_tree, cudaFuncAttributeMaxDynamicSharedMemorySize, SMEM34);
    k34_conv_tree<<<(T_DATA + TB3 - 1) / TB3, NT3, SMEM34>>>(Z, Theta, out);  // 148 blocks

    k5_vout<<<(T_DATA + TB5 - 1) / TB5, TB5>>>(out);       // 139 blocks
}